// round 1
// baseline (speedup 1.0000x reference)
#include <cuda_runtime.h>

// Problem constants (static shapes from reference)
#define BB 8
#define NN 9216
#define FF 1024
#define KK 4096

// Scratch (no allocations allowed -> device globals)
__device__ int g_vox[BB * NN];        // compact voxel id per point
__device__ int g_sorted[BB * NN];     // point indices grouped by voxel (counting sort)
__device__ int g_slotStart[BB * KK];  // per output slot (rank): start into g_sorted
__device__ int g_slotCnt[BB * KK];    // per output slot (rank): #points (0 => empty slot)
__device__ int g_count[BB];           // occupied voxels per batch

// ---------------------------------------------------------------------------
// build_kernel: one block per batch.
//  1) voxelize points, smem histogram over 4096 compact ids
//  2) dual scan (packed: low 16 bits = point-count prefix, high bits = occupancy
//     prefix == rank). 9216 < 2^16 and 9216 + 4096<<16 < 2^31 so packing is safe.
//  3) write slotStart/slotCnt indexed by rank; counting-sort point indices.
// NOTE: per-batch min subtraction in the reference is a per-axis constant shift:
// it changes ids but neither grouping nor lexicographic order, hence ranks are
// unchanged. Compact id cx*256+cy*16+cz preserves the HASH_M=1024 ordering.
// ---------------------------------------------------------------------------
__global__ __launch_bounds__(1024) void build_kernel(const float* __restrict__ xyz) {
    __shared__ int hist[KK];
    __shared__ int wsum[32];
    __shared__ int s_tot;

    const int b = blockIdx.x;
    const int tid = threadIdx.x;

    // zero histogram and slot counts (slots >= #occupied must be 0 => zero rows)
    for (int v = tid; v < KK; v += 1024) {
        hist[v] = 0;
        g_slotCnt[b * KK + v] = 0;
    }
    __syncthreads();

    // voxelize + histogram
    const float* bx = xyz + (size_t)b * NN * 3;
    for (int i = tid; i < NN; i += 1024) {
        float x = bx[i * 3 + 0];
        float y = bx[i * 3 + 1];
        float z = bx[i * 3 + 2];
        // match IEEE f32 division by 0.2f exactly (no fast-math reciprocal)
        int cx = (int)floorf(__fdiv_rn(x, 0.2f));
        int cy = (int)floorf(__fdiv_rn(y, 0.2f));
        int cz = (int)floorf(__fdiv_rn(z, 0.2f));
        cx = min(max(cx, 0), 15);
        cy = min(max(cy, 0), 15);
        cz = min(max(cz, 0), 15);
        int v = (cx << 8) | (cy << 4) | cz;
        g_vox[b * NN + i] = v;
        atomicAdd(&hist[v], 1);
    }
    __syncthreads();

    // packed dual exclusive scan over 4096 bins, 4 bins/thread
    const int base = tid * 4;
    int x0 = hist[base + 0];
    int x1 = hist[base + 1];
    int x2 = hist[base + 2];
    int x3 = hist[base + 3];
    int e0 = x0 | ((x0 > 0) << 16);
    int e1 = x1 | ((x1 > 0) << 16);
    int e2 = x2 | ((x2 > 0) << 16);
    int e3 = x3 | ((x3 > 0) << 16);
    int ts = e0 + e1 + e2 + e3;

    const int lane = tid & 31;
    const int wid = tid >> 5;

    // warp inclusive scan of thread sums
    int incl = ts;
#pragma unroll
    for (int off = 1; off < 32; off <<= 1) {
        int n = __shfl_up_sync(0xffffffffu, incl, off);
        if (lane >= off) incl += n;
    }
    if (lane == 31) wsum[wid] = incl;
    __syncthreads();

    if (wid == 0) {
        int wv = wsum[lane];
        int wi = wv;
#pragma unroll
        for (int off = 1; off < 32; off <<= 1) {
            int n = __shfl_up_sync(0xffffffffu, wi, off);
            if (lane >= off) wi += n;
        }
        wsum[lane] = wi - wv;  // exclusive warp prefix
        if (lane == 31) s_tot = wi;
    }
    __syncthreads();

    const int exBase = wsum[wid] + (incl - ts);  // exclusive prefix for this thread
    int pref0 = exBase;
    int pref1 = pref0 + e0;
    int pref2 = pref1 + e1;
    int pref3 = pref2 + e2;

    // write slot tables, reset hist[v] to the point-start offset for the scatter
    {
        int prefs[4] = {pref0, pref1, pref2, pref3};
        int cnts[4] = {x0, x1, x2, x3};
#pragma unroll
        for (int j = 0; j < 4; j++) {
            int start = prefs[j] & 0xFFFF;
            int rank = prefs[j] >> 16;
            int c = cnts[j];
            if (c > 0) {
                g_slotStart[b * KK + rank] = start;
                g_slotCnt[b * KK + rank] = c;
            }
            hist[base + j] = start;
        }
    }
    if (tid == 0) g_count[b] = (s_tot >> 16);
    __syncthreads();

    // counting-sort scatter of point indices
    for (int i = tid; i < NN; i += 1024) {
        int v = g_vox[b * NN + i];
        int pos = atomicAdd(&hist[v], 1);
        g_sorted[b * NN + pos] = i;
    }
}

// ---------------------------------------------------------------------------
// pool_kernel: one block per output row (b, rank). 256 threads * float4 = 1024
// floats. Gathers the (few) point rows of this voxel, averages, writes once.
// Empty slots write zeros (d_out is poisoned). 4-way point unroll for MLP.
// ---------------------------------------------------------------------------
__global__ __launch_bounds__(256) void pool_kernel(const float* __restrict__ feat,
                                                   float* __restrict__ out) {
    const int r = blockIdx.x;
    const int b = blockIdx.y;
    const int slot = b * KK + r;
    const int t = threadIdx.x;

    float4* o = reinterpret_cast<float4*>(out) + (size_t)slot * (FF / 4);
    const int cnt = g_slotCnt[slot];
    if (cnt == 0) {
        o[t] = make_float4(0.f, 0.f, 0.f, 0.f);
        return;
    }

    const int start = g_slotStart[slot];
    const int* sp = g_sorted + b * NN + start;
    const float4* fb = reinterpret_cast<const float4*>(feat) + (size_t)b * NN * (FF / 4);

    __shared__ int sidx[256];
    float4 acc = make_float4(0.f, 0.f, 0.f, 0.f);

    for (int bj = 0; bj < cnt; bj += 256) {
        int m = min(256, cnt - bj);
        if (t < m) sidx[t] = sp[bj + t];
        __syncthreads();
        int j = 0;
        for (; j + 3 < m; j += 4) {
            int i0 = sidx[j + 0], i1 = sidx[j + 1], i2 = sidx[j + 2], i3 = sidx[j + 3];
            float4 v0 = fb[(size_t)i0 * (FF / 4) + t];
            float4 v1 = fb[(size_t)i1 * (FF / 4) + t];
            float4 v2 = fb[(size_t)i2 * (FF / 4) + t];
            float4 v3 = fb[(size_t)i3 * (FF / 4) + t];
            acc.x += v0.x; acc.y += v0.y; acc.z += v0.z; acc.w += v0.w;
            acc.x += v1.x; acc.y += v1.y; acc.z += v1.z; acc.w += v1.w;
            acc.x += v2.x; acc.y += v2.y; acc.z += v2.z; acc.w += v2.w;
            acc.x += v3.x; acc.y += v3.y; acc.z += v3.z; acc.w += v3.w;
        }
        for (; j < m; j++) {
            float4 v = fb[(size_t)sidx[j] * (FF / 4) + t];
            acc.x += v.x; acc.y += v.y; acc.z += v.z; acc.w += v.w;
        }
        __syncthreads();
    }

    float inv = 1.0f / (float)cnt;
    o[t] = make_float4(acc.x * inv, acc.y * inv, acc.z * inv, acc.w * inv);
}

// batch_offset = cumsum(counts), written as float after the pooled block
__global__ void offsets_kernel(float* __restrict__ out_tail) {
    if (threadIdx.x == 0 && blockIdx.x == 0) {
        int acc = 0;
#pragma unroll
        for (int b = 0; b < BB; b++) {
            acc += g_count[b];
            out_tail[b] = (float)acc;
        }
    }
}

extern "C" void kernel_launch(void* const* d_in, const int* in_sizes, int n_in,
                              void* d_out, int out_size) {
    // metadata order: features (B*N*F), xyz (B*N*3). Be defensive via sizes.
    const float* features = (const float*)d_in[0];
    const float* xyz = (const float*)d_in[1];
    if (n_in >= 2 && in_sizes[0] < in_sizes[1]) {
        features = (const float*)d_in[1];
        xyz = (const float*)d_in[0];
    }
    float* out = (float*)d_out;

    build_kernel<<<BB, 1024>>>(xyz);
    dim3 grid(KK, BB);
    pool_kernel<<<grid, 256>>>(features, out);
    if (out_size > BB * KK * FF) {
        offsets_kernel<<<1, 1>>>(out + (size_t)BB * KK * FF);
    }
}

// round 2
// speedup vs baseline: 1.0229x; 1.0229x over previous
#include <cuda_runtime.h>

#define BB 8
#define NN 9216
#define FF 1024
#define KK 4096

// Scratch (device globals; no allocations allowed)
__device__ int  g_hist[BB * KK];    // per-batch voxel histogram
__device__ int  g_off[BB * KK];     // running point offset per voxel (scatter cursor)
__device__ int2 g_slotSC[BB * KK];  // per output slot (rank): {start into g_sorted, count}
__device__ int  g_sorted[BB * NN];  // point indices grouped by voxel
__device__ int  g_count[BB];        // occupied voxels per batch

// Compact voxel id: cx*256+cy*16+cz preserves the reference HASH_M=1024
// lexicographic ordering; the per-batch min subtraction is a per-axis constant
// shift and changes neither grouping nor order, hence ranks are unchanged.
__device__ __forceinline__ int voxel_id(const float* __restrict__ bx, int i) {
    float x = bx[i * 3 + 0];
    float y = bx[i * 3 + 1];
    float z = bx[i * 3 + 2];
    int cx = (int)floorf(__fdiv_rn(x, 0.2f));
    int cy = (int)floorf(__fdiv_rn(y, 0.2f));
    int cz = (int)floorf(__fdiv_rn(z, 0.2f));
    cx = min(max(cx, 0), 15);
    cy = min(max(cy, 0), 15);
    cz = min(max(cz, 0), 15);
    return (cx << 8) | (cy << 4) | cz;
}

// 1) zero the histograms (128 KB)
__global__ void zero_kernel() {
    int i = blockIdx.x * blockDim.x + threadIdx.x;
    if (i < BB * KK) g_hist[i] = 0;
}

// 2) voxelize + global histogram, grid (9, BB) x 1024
__global__ __launch_bounds__(1024) void voxhist_kernel(const float* __restrict__ xyz) {
    const int b = blockIdx.y;
    const int i = blockIdx.x * 1024 + threadIdx.x;
    if (i >= NN) return;
    const float* bx = xyz + (size_t)b * NN * 3;
    int v = voxel_id(bx, i);
    atomicAdd(&g_hist[b * KK + v], 1);
}

// 3) per-batch packed dual exclusive scan over 4096 bins (4 bins/thread).
//    low 16 bits: point-count prefix (<= 9216 < 2^16); high bits: occupancy
//    prefix == compacted rank. Writes slot table + scatter cursors + count.
__global__ __launch_bounds__(1024) void scan_kernel() {
    __shared__ int wsum[32];
    __shared__ int s_tot;

    const int b = blockIdx.x;
    const int tid = threadIdx.x;

    // zero the full slot table (empty slots must yield zero rows)
    {
        int2 z = make_int2(0, 0);
#pragma unroll
        for (int j = 0; j < 4; j++) g_slotSC[b * KK + tid * 4 + j] = z;
    }

    const int base = tid * 4;
    int x0 = g_hist[b * KK + base + 0];
    int x1 = g_hist[b * KK + base + 1];
    int x2 = g_hist[b * KK + base + 2];
    int x3 = g_hist[b * KK + base + 3];
    int e0 = x0 | ((x0 > 0) << 16);
    int e1 = x1 | ((x1 > 0) << 16);
    int e2 = x2 | ((x2 > 0) << 16);
    int e3 = x3 | ((x3 > 0) << 16);
    int ts = e0 + e1 + e2 + e3;

    const int lane = tid & 31;
    const int wid = tid >> 5;

    int incl = ts;
#pragma unroll
    for (int off = 1; off < 32; off <<= 1) {
        int n = __shfl_up_sync(0xffffffffu, incl, off);
        if (lane >= off) incl += n;
    }
    if (lane == 31) wsum[wid] = incl;
    __syncthreads();

    if (wid == 0) {
        int wv = wsum[lane];
        int wi = wv;
#pragma unroll
        for (int off = 1; off < 32; off <<= 1) {
            int n = __shfl_up_sync(0xffffffffu, wi, off);
            if (lane >= off) wi += n;
        }
        wsum[lane] = wi - wv;
        if (lane == 31) s_tot = wi;
    }
    __syncthreads();

    const int exBase = wsum[wid] + (incl - ts);
    int prefs[4];
    prefs[0] = exBase;
    prefs[1] = prefs[0] + e0;
    prefs[2] = prefs[1] + e1;
    prefs[3] = prefs[2] + e2;
    int cnts[4] = {x0, x1, x2, x3};

#pragma unroll
    for (int j = 0; j < 4; j++) {
        int start = prefs[j] & 0xFFFF;
        int rank = prefs[j] >> 16;
        int c = cnts[j];
        if (c > 0) g_slotSC[b * KK + rank] = make_int2(start, c);
        g_off[b * KK + base + j] = start;  // scatter cursor (indexed by voxel id)
    }
    if (tid == 0) g_count[b] = (s_tot >> 16);
}

// 4) counting-sort scatter of point indices, grid (9, BB) x 1024
__global__ __launch_bounds__(1024) void scatter_kernel(const float* __restrict__ xyz) {
    const int b = blockIdx.y;
    const int i = blockIdx.x * 1024 + threadIdx.x;
    if (i >= NN) return;
    const float* bx = xyz + (size_t)b * NN * 3;
    int v = voxel_id(bx, i);
    int pos = atomicAdd(&g_off[b * KK + v], 1);
    g_sorted[b * NN + pos] = i;
}

// 5) pool: one block per output row (b, rank). 256 threads x float4 = 1024
//    floats. Per-warp coalesced index load + shuffle broadcast -> all cnt
//    feature loads are independent (MLP = cnt), no barriers, no smem.
__global__ __launch_bounds__(256) void pool_kernel(const float* __restrict__ feat,
                                                   float* __restrict__ out) {
    const int r = blockIdx.x;
    const int b = blockIdx.y;
    const int slot = b * KK + r;
    const int t = threadIdx.x;
    const int lane = t & 31;

    float4* o = reinterpret_cast<float4*>(out) + (size_t)slot * (FF / 4);
    const int2 sc = g_slotSC[slot];
    const int cnt = sc.y;
    if (cnt == 0) {
        o[t] = make_float4(0.f, 0.f, 0.f, 0.f);
        return;
    }

    const int* sp = g_sorted + b * NN + sc.x;
    const float4* fb = reinterpret_cast<const float4*>(feat) + (size_t)b * NN * (FF / 4);

    float4 acc = make_float4(0.f, 0.f, 0.f, 0.f);
    for (int base = 0; base < cnt; base += 32) {
        int m = min(32, cnt - base);
        int myidx = (lane < m) ? sp[base + lane] : 0;
#pragma unroll 4
        for (int j = 0; j < m; j++) {
            int idx = __shfl_sync(0xffffffffu, myidx, j);
            float4 v = fb[(size_t)idx * (FF / 4) + t];
            acc.x += v.x; acc.y += v.y; acc.z += v.z; acc.w += v.w;
        }
    }

    float inv = 1.0f / (float)cnt;
    o[t] = make_float4(acc.x * inv, acc.y * inv, acc.z * inv, acc.w * inv);
}

// 6) batch_offset = cumsum(counts), written as float after the pooled block
__global__ void offsets_kernel(float* __restrict__ out_tail) {
    if (threadIdx.x == 0 && blockIdx.x == 0) {
        int acc = 0;
#pragma unroll
        for (int b = 0; b < BB; b++) {
            acc += g_count[b];
            out_tail[b] = (float)acc;
        }
    }
}

extern "C" void kernel_launch(void* const* d_in, const int* in_sizes, int n_in,
                              void* d_out, int out_size) {
    const float* features = (const float*)d_in[0];
    const float* xyz = (const float*)d_in[1];
    if (n_in >= 2 && in_sizes[0] < in_sizes[1]) {
        features = (const float*)d_in[1];
        xyz = (const float*)d_in[0];
    }
    float* out = (float*)d_out;

    zero_kernel<<<(BB * KK + 1023) / 1024, 1024>>>();
    dim3 gvox(9, BB);
    voxhist_kernel<<<gvox, 1024>>>(xyz);
    scan_kernel<<<BB, 1024>>>();
    scatter_kernel<<<gvox, 1024>>>(xyz);
    dim3 gpool(KK, BB);
    pool_kernel<<<gpool, 256>>>(features, out);
    if (out_size > BB * KK * FF) {
        offsets_kernel<<<1, 1>>>(out + (size_t)BB * KK * FF);
    }
}

// round 3
// speedup vs baseline: 1.1401x; 1.1146x over previous
#include <cuda_runtime.h>

#define BB 8
#define NN 9216
#define FF 1024
#define KK 4096

// Scratch (device globals; no allocations allowed)
__device__ int  g_hist[BB * KK];    // per-batch voxel histogram (zero-invariant across calls)
__device__ int  g_off[BB * KK];     // running point offset per voxel (scatter cursor)
__device__ int2 g_slotSC[BB * KK];  // per output slot (rank): {start into g_sorted, count}
__device__ int  g_sorted[BB * NN];  // point indices grouped by voxel
__device__ int  g_count[BB];        // occupied voxels per batch

// Compact voxel id: cx*256+cy*16+cz preserves the reference HASH_M=1024
// lexicographic ordering; the per-batch min subtraction is a per-axis constant
// shift and changes neither grouping nor order, hence ranks are unchanged.
__device__ __forceinline__ int voxel_id(const float* __restrict__ bx, int i) {
    float x = bx[i * 3 + 0];
    float y = bx[i * 3 + 1];
    float z = bx[i * 3 + 2];
    int cx = (int)floorf(__fdiv_rn(x, 0.2f));
    int cy = (int)floorf(__fdiv_rn(y, 0.2f));
    int cz = (int)floorf(__fdiv_rn(z, 0.2f));
    cx = min(max(cx, 0), 15);
    cy = min(max(cy, 0), 15);
    cz = min(max(cz, 0), 15);
    return (cx << 8) | (cy << 4) | cz;
}

// 1) voxelize + global histogram. grid (9, BB) x 256, 4 points/thread for MLP.
//    g_hist is zero on entry (module-load zero init; scan re-zeroes it).
__global__ __launch_bounds__(256) void voxhist_kernel(const float* __restrict__ xyz) {
    const int b = blockIdx.y;
    const int i0 = blockIdx.x * 1024 + threadIdx.x;
    const float* bx = xyz + (size_t)b * NN * 3;
#pragma unroll
    for (int j = 0; j < 4; j++) {
        int i = i0 + j * 256;
        if (i < NN) {
            int v = voxel_id(bx, i);
            atomicAdd(&g_hist[b * KK + v], 1);
        }
    }
}

// 2) per-batch packed dual exclusive scan over 4096 bins (4 bins/thread).
//    low 16 bits: point-count prefix (<= 9216 < 2^16); high bits: occupancy
//    prefix == compacted rank. Writes slot table + scatter cursors + count,
//    and re-zeroes g_hist to keep the cross-launch invariant.
__global__ __launch_bounds__(1024) void scan_kernel() {
    __shared__ int wsum[32];
    __shared__ int s_tot;

    const int b = blockIdx.x;
    const int tid = threadIdx.x;

    // zero the full slot table (empty slots must yield zero rows)
    {
        int2 z = make_int2(0, 0);
#pragma unroll
        for (int j = 0; j < 4; j++) g_slotSC[b * KK + tid * 4 + j] = z;
    }

    const int base = tid * 4;
    int x0 = g_hist[b * KK + base + 0];
    int x1 = g_hist[b * KK + base + 1];
    int x2 = g_hist[b * KK + base + 2];
    int x3 = g_hist[b * KK + base + 3];
    int e0 = x0 | ((x0 > 0) << 16);
    int e1 = x1 | ((x1 > 0) << 16);
    int e2 = x2 | ((x2 > 0) << 16);
    int e3 = x3 | ((x3 > 0) << 16);
    int ts = e0 + e1 + e2 + e3;

    const int lane = tid & 31;
    const int wid = tid >> 5;

    int incl = ts;
#pragma unroll
    for (int off = 1; off < 32; off <<= 1) {
        int n = __shfl_up_sync(0xffffffffu, incl, off);
        if (lane >= off) incl += n;
    }
    if (lane == 31) wsum[wid] = incl;
    __syncthreads();

    if (wid == 0) {
        int wv = wsum[lane];
        int wi = wv;
#pragma unroll
        for (int off = 1; off < 32; off <<= 1) {
            int n = __shfl_up_sync(0xffffffffu, wi, off);
            if (lane >= off) wi += n;
        }
        wsum[lane] = wi - wv;
        if (lane == 31) s_tot = wi;
    }
    __syncthreads();

    const int exBase = wsum[wid] + (incl - ts);
    int prefs[4];
    prefs[0] = exBase;
    prefs[1] = prefs[0] + e0;
    prefs[2] = prefs[1] + e1;
    prefs[3] = prefs[2] + e2;
    int cnts[4] = {x0, x1, x2, x3};

#pragma unroll
    for (int j = 0; j < 4; j++) {
        int start = prefs[j] & 0xFFFF;
        int rank = prefs[j] >> 16;
        int c = cnts[j];
        if (c > 0) g_slotSC[b * KK + rank] = make_int2(start, c);
        g_off[b * KK + base + j] = start;  // scatter cursor (indexed by voxel id)
        g_hist[b * KK + base + j] = 0;     // restore zero-invariant for next call
    }
    if (tid == 0) g_count[b] = (s_tot >> 16);
}

// 3) counting-sort scatter of point indices. grid (9, BB) x 256, 4 pts/thread.
__global__ __launch_bounds__(256) void scatter_kernel(const float* __restrict__ xyz) {
    const int b = blockIdx.y;
    const int i0 = blockIdx.x * 1024 + threadIdx.x;
    const float* bx = xyz + (size_t)b * NN * 3;
#pragma unroll
    for (int j = 0; j < 4; j++) {
        int i = i0 + j * 256;
        if (i < NN) {
            int v = voxel_id(bx, i);
            int pos = atomicAdd(&g_off[b * KK + v], 1);
            g_sorted[b * NN + pos] = i;
        }
    }
}

// 4) pool: one block per TWO output rows (b, 2r / 2r+1). 256 threads x float4.
//    Per-warp coalesced index load + shuffle broadcast -> all cnt feature loads
//    independent; streaming loads/stores (no L2 reuse anywhere).
__global__ __launch_bounds__(256) void pool_kernel(const float* __restrict__ feat,
                                                   float* __restrict__ out) {
    const int b = blockIdx.y;
    const int t = threadIdx.x;
    const int lane = t & 31;
    const float4* fb = reinterpret_cast<const float4*>(feat) + (size_t)b * NN * (FF / 4);

#pragma unroll
    for (int s = 0; s < 2; s++) {
        const int slot = b * KK + blockIdx.x * 2 + s;
        float4* o = reinterpret_cast<float4*>(out) + (size_t)slot * (FF / 4);
        const int2 sc = g_slotSC[slot];
        const int cnt = sc.y;
        if (cnt == 0) {
            __stcs(&o[t], make_float4(0.f, 0.f, 0.f, 0.f));
            continue;
        }

        const int* sp = g_sorted + b * NN + sc.x;
        float4 acc = make_float4(0.f, 0.f, 0.f, 0.f);
        for (int base = 0; base < cnt; base += 32) {
            int m = min(32, cnt - base);
            int myidx = (lane < m) ? sp[base + lane] : 0;
#pragma unroll 4
            for (int j = 0; j < m; j++) {
                int idx = __shfl_sync(0xffffffffu, myidx, j);
                float4 v = __ldcs(&fb[(size_t)idx * (FF / 4) + t]);
                acc.x += v.x; acc.y += v.y; acc.z += v.z; acc.w += v.w;
            }
        }

        float inv = 1.0f / (float)cnt;
        __stcs(&o[t], make_float4(acc.x * inv, acc.y * inv, acc.z * inv, acc.w * inv));
    }
}

// 5) batch_offset = cumsum(counts), written as float after the pooled block
__global__ void offsets_kernel(float* __restrict__ out_tail) {
    if (threadIdx.x == 0 && blockIdx.x == 0) {
        int acc = 0;
#pragma unroll
        for (int b = 0; b < BB; b++) {
            acc += g_count[b];
            out_tail[b] = (float)acc;
        }
    }
}

extern "C" void kernel_launch(void* const* d_in, const int* in_sizes, int n_in,
                              void* d_out, int out_size) {
    const float* features = (const float*)d_in[0];
    const float* xyz = (const float*)d_in[1];
    if (n_in >= 2 && in_sizes[0] < in_sizes[1]) {
        features = (const float*)d_in[1];
        xyz = (const float*)d_in[0];
    }
    float* out = (float*)d_out;

    dim3 gvox(9, BB);
    voxhist_kernel<<<gvox, 256>>>(xyz);
    scan_kernel<<<BB, 1024>>>();
    scatter_kernel<<<gvox, 256>>>(xyz);
    dim3 gpool(KK / 2, BB);
    pool_kernel<<<gpool, 256>>>(features, out);
    if (out_size > BB * KK * FF) {
        offsets_kernel<<<1, 1>>>(out + (size_t)BB * KK * FF);
    }
}